// round 11
// baseline (speedup 1.0000x reference)
#include <cuda_runtime.h>
#include <cuda_bf16.h>
#include <cstdint>

// Router: logits = x @ W^T via split-bf16 mma.sync (3 terms), warp-specialized
// 3-stage producer/consumer ring. W pre-converted to bf16 hi/lo once per launch.
// Outputs concatenated fp32: mask[T*64] | idx[T*2] | router_probs[T*64] | probs[T*64]

#define THREADS 768       // warps 0-15 consumers, 16-23 producers
#define TM 128            // tokens per CTA
#define CK 64             // K chunk
#define NCH (2048 / CK)   // 32
#define NSTG 3            // ring stages
#define ASTR 144          // smem row stride bytes (64 bf16 = 128B + 16 pad)

// per-stage smem layout (bytes)
#define AHI_O 0
#define ALO_O 18432       // 128*144
#define BHI_O 36864
#define BLO_O 46080       // +64*144
#define BUFSZ 55296
#define SMEMB (NSTG * BUFSZ)   // 165888
#define LS 68             // logits row stride (floats)

typedef unsigned long long ull;

__device__ __nv_bfloat16 g_Whi[64 * 2048];
__device__ __nv_bfloat16 g_Wlo[64 * 2048];

#define BAR_SYNC(id)   asm volatile("bar.sync %0, 768;"   :: "r"(id) : "memory")
#define BAR_ARRIVE(id) asm volatile("bar.arrive %0, 768;" :: "r"(id) : "memory")

__device__ __forceinline__ uint32_t smem_u32(const void* p) {
    uint32_t a;
    asm("{ .reg .u64 t; cvta.to.shared.u64 t, %1; cvt.u32.u64 %0, t; }"
        : "=r"(a) : "l"(p));
    return a;
}

__device__ __forceinline__ void ldm4(uint32_t* r, uint32_t addr) {
    asm volatile("ldmatrix.sync.aligned.m8n8.x4.shared.b16 {%0,%1,%2,%3}, [%4];"
        : "=r"(r[0]), "=r"(r[1]), "=r"(r[2]), "=r"(r[3]) : "r"(addr));
}

// register-only, non-volatile: ptxas may schedule freely
__device__ __forceinline__ void mma16816(float* d, const uint32_t* a,
                                         uint32_t b0, uint32_t b1) {
    asm("mma.sync.aligned.m16n8k16.row.col.f32.bf16.bf16.f32 "
        "{%0,%1,%2,%3}, {%4,%5,%6,%7}, {%8,%9}, {%0,%1,%2,%3};"
        : "+f"(d[0]), "+f"(d[1]), "+f"(d[2]), "+f"(d[3])
        : "r"(a[0]), "r"(a[1]), "r"(a[2]), "r"(a[3]), "r"(b0), "r"(b1));
}

// fp32x4 -> bf16 hi x4 (8B) + bf16 lo x4 (8B)
__device__ __forceinline__ void split4(float4 v, ull& H, ull& L) {
    uint32_t hu0, hu1;
    asm("cvt.rn.bf16x2.f32 %0, %1, %2;" : "=r"(hu0) : "f"(v.y), "f"(v.x));
    asm("cvt.rn.bf16x2.f32 %0, %1, %2;" : "=r"(hu1) : "f"(v.w), "f"(v.z));
    const float h0 = __uint_as_float(hu0 << 16);
    const float h1 = __uint_as_float(hu0 & 0xffff0000u);
    const float h2 = __uint_as_float(hu1 << 16);
    const float h3 = __uint_as_float(hu1 & 0xffff0000u);
    uint32_t gu0, gu1;
    asm("cvt.rn.bf16x2.f32 %0, %1, %2;" : "=r"(gu0) : "f"(v.y - h1), "f"(v.x - h0));
    asm("cvt.rn.bf16x2.f32 %0, %1, %2;" : "=r"(gu1) : "f"(v.w - h3), "f"(v.z - h2));
    asm("mov.b64 %0, {%1, %2};" : "=l"(H) : "r"(hu0), "r"(hu1));
    asm("mov.b64 %0, {%1, %2};" : "=l"(L) : "r"(gu0), "r"(gu1));
}

__device__ __forceinline__ void cvt_store(uint32_t hi_addr, uint32_t lo_addr, float4 v) {
    ull H, L;
    split4(v, H, L);
    asm volatile("st.shared.b64 [%0], %1;" :: "r"(hi_addr), "l"(H) : "memory");
    asm volatile("st.shared.b64 [%0], %1;" :: "r"(lo_addr), "l"(L) : "memory");
}

// ---- pre-kernel: convert W (64x2048 fp32) -> bf16 hi/lo ----
__global__ void __launch_bounds__(256)
wprep_kernel(const float* __restrict__ W)
{
    const int i = blockIdx.x * 256 + threadIdx.x;   // 0..32767 float4s
    const float4 v = reinterpret_cast<const float4*>(W)[i];
    ull H, L;
    split4(v, H, L);
    reinterpret_cast<ull*>(g_Whi)[i] = H;
    reinterpret_cast<ull*>(g_Wlo)[i] = L;
}

__global__ void __launch_bounds__(THREADS, 1)
router_kernel(const float* __restrict__ x, float* __restrict__ out, int T)
{
    extern __shared__ __align__(128) char dsm[];
    const uint32_t sb = smem_u32(dsm);

    const int tid = threadIdx.x;
    const int wid = tid >> 5;
    const int lane = tid & 31;
    const int row0 = blockIdx.x * TM;

    // barrier ids: full[s]=1+s (1..3), empty[s]=4+s (4..6)
    float d[4][4];
#pragma unroll
    for (int g = 0; g < 4; g++)
#pragma unroll
        for (int j = 0; j < 4; j++) d[g][j] = 0.f;

    if (wid >= 16) {
        // ================= PRODUCER (warps 16-23, 256 threads) =================
        const int tp = tid - 512;   // 0..255
        float4 ax[8];
        uint4 bh[2], bl[2];

        // load chunk 0
#pragma unroll
        for (int i = 0; i < 8; i++) {
            const int f = i * 256 + tp;              // 0..2047
            const int grow = row0 + (f >> 4);        // rows 0..127
            ax[i] = (grow < T)
                ? *reinterpret_cast<const float4*>(x + (size_t)grow * 2048 + (f & 15) * 4)
                : make_float4(0.f, 0.f, 0.f, 0.f);
        }
#pragma unroll
        for (int i = 0; i < 2; i++) {
            const int f = i * 256 + tp;              // 0..511
            const int rr = f >> 3;                   // 0..63
            const int cc = f & 7;                    // uint4 col
            bh[i] = *reinterpret_cast<const uint4*>(g_Whi + (size_t)rr * 2048 + cc * 8);
            bl[i] = *reinterpret_cast<const uint4*>(g_Wlo + (size_t)rr * 2048 + cc * 8);
        }

        for (int c = 0; c < NCH; c++) {
            const int s = c % NSTG;
            const uint32_t off = (uint32_t)s * BUFSZ;
            const uint32_t tb = sb + off;

            if (c >= NSTG) BAR_SYNC(4 + s);   // wait consumer freed this stage

            // store staged chunk c
#pragma unroll
            for (int i = 0; i < 8; i++) {
                const int f = i * 256 + tp;
                const uint32_t o = (uint32_t)((f >> 4) * ASTR + (f & 15) * 8);
                cvt_store(tb + AHI_O + o, tb + ALO_O + o, ax[i]);
            }
#pragma unroll
            for (int i = 0; i < 2; i++) {
                const int f = i * 256 + tp;
                const uint32_t o = (uint32_t)((f >> 3) * ASTR + (f & 7) * 16);
                *reinterpret_cast<uint4*>(dsm + off + BHI_O + o) = bh[i];
                *reinterpret_cast<uint4*>(dsm + off + BLO_O + o) = bl[i];
            }
            asm volatile("membar.cta;" ::: "memory");
            BAR_ARRIVE(1 + s);             // stage full

            // prefetch chunk c+1 (LDG latency hidden behind ring slack)
            if (c + 1 < NCH) {
                const int k0 = (c + 1) * CK;
#pragma unroll
                for (int i = 0; i < 8; i++) {
                    const int f = i * 256 + tp;
                    const int grow = row0 + (f >> 4);
                    if (grow < T)
                        ax[i] = *reinterpret_cast<const float4*>(
                            x + (size_t)grow * 2048 + k0 + (f & 15) * 4);
                }
#pragma unroll
                for (int i = 0; i < 2; i++) {
                    const int f = i * 256 + tp;
                    const int rr = f >> 3;
                    const int cc = f & 7;
                    bh[i] = *reinterpret_cast<const uint4*>(
                        g_Whi + (size_t)rr * 2048 + k0 + cc * 8);
                    bl[i] = *reinterpret_cast<const uint4*>(
                        g_Wlo + (size_t)rr * 2048 + k0 + cc * 8);
                }
            }
        }
    } else {
        // ================= CONSUMER (warps 0-15) =================
        // warp strip: tokens (wid>>1)*16 .. +15, experts (wid&1)*32 .. +31
        const int sr = (wid >> 1) * 16;
        const int eh = (wid & 1) * 32;

        const uint32_t a_base = (uint32_t)((sr + (lane & 15)) * ASTR
                                           + ((lane >> 4) << 4));
        const uint32_t b_base = (uint32_t)((eh + (lane & 7) + ((lane >> 4) & 1) * 8) * ASTR
                                           + (((lane >> 3) & 1) << 4));

        for (int c = 0; c < NCH; c++) {
            const int s = c % NSTG;
            const uint32_t tb = sb + (uint32_t)s * BUFSZ;
            BAR_SYNC(1 + s);               // wait stage full
#pragma unroll
            for (int kk = 0; kk < 4; kk++) {
                const uint32_t ko = kk * 32;
                uint32_t ah[4], al[4];
                ldm4(ah, tb + AHI_O + a_base + ko);
                ldm4(al, tb + ALO_O + a_base + ko);
#pragma unroll
                for (int j = 0; j < 2; j++) {
                    uint32_t vh[4], vl[4];
                    const uint32_t bo = b_base + (uint32_t)(j * 16 * ASTR) + ko;
                    ldm4(vh, tb + BHI_O + bo);
                    ldm4(vl, tb + BLO_O + bo);
#pragma unroll
                    for (int tt = 0; tt < 2; tt++) {
                        float* dd = d[j * 2 + tt];
                        mma16816(dd, ah, vh[tt * 2], vh[tt * 2 + 1]);
                        mma16816(dd, ah, vl[tt * 2], vl[tt * 2 + 1]);
                        mma16816(dd, al, vh[tt * 2], vh[tt * 2 + 1]);
                    }
                }
            }
            BAR_ARRIVE(4 + s);             // stage free
        }
    }

    __syncthreads();

    // ---- dump logits to smem [TM][LS] (consumer warps only) ----
    float* lg = reinterpret_cast<float*>(dsm);
    if (wid < 16) {
        const int sr = (wid >> 1) * 16;
        const int eh = (wid & 1) * 32;
        const int r1 = sr + (lane >> 2);     // 0..127
        const int n0 = eh + 2 * (lane & 3);
#pragma unroll
        for (int g = 0; g < 4; g++) {
            const int ec = n0 + (g >> 1) * 16 + (g & 1) * 8;   // g = j*2+tt
            *reinterpret_cast<float2*>(lg + r1 * LS + ec) =
                make_float2(d[g][0], d[g][1]);
            *reinterpret_cast<float2*>(lg + (r1 + 8) * LS + ec) =
                make_float2(d[g][2], d[g][3]);
        }
    }
    __syncthreads();

    // ---- epilogue: one thread = one token (threads 0..127) ----
    if (tid >= TM) return;
    const int row = row0 + tid;
    if (row >= T) return;

    float l[64];
#pragma unroll
    for (int e = 0; e < 64; e += 4) {
        const float4 v = *reinterpret_cast<const float4*>(lg + tid * LS + e);
        l[e] = v.x; l[e + 1] = v.y; l[e + 2] = v.z; l[e + 3] = v.w;
    }

    // top-2 (earliest index wins ties, matching lax.top_k)
    float m1 = -3.402823466e38f, m2 = -3.402823466e38f;
    int i1 = 0, i2 = 0;
#pragma unroll
    for (int e = 0; e < 64; e++) {
        const float v = l[e];
        if (v > m1) { m2 = m1; i2 = i1; m1 = v; i1 = e; }
        else if (v > m2) { m2 = v; i2 = e; }
    }

    float s = 0.f;
    float p[64];
#pragma unroll
    for (int e = 0; e < 64; e++) {
        p[e] = __expf(l[e] - m1);
        s += p[e];
    }
    const float inv = 1.0f / s;

    const float p1 = p[i1] * inv;
    const float p2 = p[i2] * inv;
    const float rs = 1.0f / (p1 + p2);

    const size_t Tz = (size_t)T;
    float* mask = out;
    float* idxo = out + Tz * 64;
    float* rp   = out + Tz * 64 + Tz * 2;
    float* pr   = out + Tz * 64 + Tz * 2 + Tz * 64;
    const size_t gt = (size_t)row;

#pragma unroll
    for (int e = 0; e < 64; e += 4) {
        float4 pv4, m4, r4;
        float* pvp = &pv4.x; float* mp = &m4.x; float* rpp = &r4.x;
#pragma unroll
        for (int j = 0; j < 4; j++) {
            const int ee = e + j;
            const float pv = p[ee] * inv;
            const bool sel = (ee == i1) | (ee == i2);
            pvp[j] = pv;
            mp[j] = sel ? 1.0f : 0.0f;
            rpp[j] = sel ? pv * rs : 0.0f;
        }
        *reinterpret_cast<float4*>(pr + gt * 64 + e) = pv4;
        *reinterpret_cast<float4*>(mask + gt * 64 + e) = m4;
        *reinterpret_cast<float4*>(rp + gt * 64 + e) = r4;
    }
    idxo[gt * 2 + 0] = (float)i1;
    idxo[gt * 2 + 1] = (float)i2;
}

extern "C" void kernel_launch(void* const* d_in, const int* in_sizes, int n_in,
                              void* d_out, int out_size)
{
    const float* x = (const float*)d_in[0];
    const float* W = (const float*)d_in[1];
    const int T = in_sizes[0] / 2048;

    wprep_kernel<<<128, 256>>>(W);

    cudaFuncSetAttribute(router_kernel,
                         cudaFuncAttributeMaxDynamicSharedMemorySize, SMEMB);
    const int blocks = (T + TM - 1) / TM;
    router_kernel<<<blocks, THREADS, SMEMB>>>(x, (float*)d_out, T);
}

// round 12
// speedup vs baseline: 1.0088x; 1.0088x over previous
#include <cuda_runtime.h>
#include <cuda_bf16.h>
#include <cstdint>

// Router: logits = x @ W^T via split-bf16 mma.sync (3 terms), warp-specialized
// 3-stage ring, 32x32 consumer warp tiles, double-buffered fragment pipeline.
// Outputs concatenated fp32: mask[T*64] | idx[T*2] | router_probs[T*64] | probs[T*64]

#define THREADS 384       // warps 0-7 consumers (32tok x 32exp), 8-11 producers
#define TM 128            // tokens per CTA
#define CK 64             // K chunk
#define NCH (2048 / CK)   // 32
#define NSTG 3            // ring stages
#define ASTR 144          // smem row stride bytes (64 bf16 = 128B + 16 pad)

// per-stage smem layout (bytes)
#define AHI_O 0
#define ALO_O 18432       // 128*144
#define BHI_O 36864
#define BLO_O 46080       // +64*144
#define BUFSZ 55296
#define SMEMB (NSTG * BUFSZ)   // 165888
#define LS 68             // logits row stride (floats)

typedef unsigned long long ull;

__device__ __nv_bfloat16 g_Whi[64 * 2048];
__device__ __nv_bfloat16 g_Wlo[64 * 2048];

#define BAR_SYNC(id)   asm volatile("bar.sync %0, 384;"   :: "r"(id) : "memory")
#define BAR_ARRIVE(id) asm volatile("bar.arrive %0, 384;" :: "r"(id) : "memory")

__device__ __forceinline__ uint32_t smem_u32(const void* p) {
    uint32_t a;
    asm("{ .reg .u64 t; cvta.to.shared.u64 t, %1; cvt.u32.u64 %0, t; }"
        : "=r"(a) : "l"(p));
    return a;
}

__device__ __forceinline__ void ldm4(uint32_t* r, uint32_t addr) {
    asm volatile("ldmatrix.sync.aligned.m8n8.x4.shared.b16 {%0,%1,%2,%3}, [%4];"
        : "=r"(r[0]), "=r"(r[1]), "=r"(r[2]), "=r"(r[3]) : "r"(addr));
}

// register-only, non-volatile: ptxas may schedule freely around the ldm4s
__device__ __forceinline__ void mma16816(float* d, const uint32_t* a,
                                         uint32_t b0, uint32_t b1) {
    asm("mma.sync.aligned.m16n8k16.row.col.f32.bf16.bf16.f32 "
        "{%0,%1,%2,%3}, {%4,%5,%6,%7}, {%8,%9}, {%0,%1,%2,%3};"
        : "+f"(d[0]), "+f"(d[1]), "+f"(d[2]), "+f"(d[3])
        : "r"(a[0]), "r"(a[1]), "r"(a[2]), "r"(a[3]), "r"(b0), "r"(b1));
}

// fp32x4 -> bf16 hi x4 (8B) + bf16 lo x4 (8B)
__device__ __forceinline__ void split4(float4 v, ull& H, ull& L) {
    uint32_t hu0, hu1;
    asm("cvt.rn.bf16x2.f32 %0, %1, %2;" : "=r"(hu0) : "f"(v.y), "f"(v.x));
    asm("cvt.rn.bf16x2.f32 %0, %1, %2;" : "=r"(hu1) : "f"(v.w), "f"(v.z));
    const float h0 = __uint_as_float(hu0 << 16);
    const float h1 = __uint_as_float(hu0 & 0xffff0000u);
    const float h2 = __uint_as_float(hu1 << 16);
    const float h3 = __uint_as_float(hu1 & 0xffff0000u);
    uint32_t gu0, gu1;
    asm("cvt.rn.bf16x2.f32 %0, %1, %2;" : "=r"(gu0) : "f"(v.y - h1), "f"(v.x - h0));
    asm("cvt.rn.bf16x2.f32 %0, %1, %2;" : "=r"(gu1) : "f"(v.w - h3), "f"(v.z - h2));
    asm("mov.b64 %0, {%1, %2};" : "=l"(H) : "r"(hu0), "r"(hu1));
    asm("mov.b64 %0, {%1, %2};" : "=l"(L) : "r"(gu0), "r"(gu1));
}

__device__ __forceinline__ void cvt_store(uint32_t hi_addr, uint32_t lo_addr, float4 v) {
    ull H, L;
    split4(v, H, L);
    asm volatile("st.shared.b64 [%0], %1;" :: "r"(hi_addr), "l"(H) : "memory");
    asm volatile("st.shared.b64 [%0], %1;" :: "r"(lo_addr), "l"(L) : "memory");
}

// ---- pre-kernel: convert W (64x2048 fp32) -> bf16 hi/lo ----
__global__ void __launch_bounds__(256)
wprep_kernel(const float* __restrict__ W)
{
    const int i = blockIdx.x * 256 + threadIdx.x;   // 0..32767 float4s
    const float4 v = reinterpret_cast<const float4*>(W)[i];
    ull H, L;
    split4(v, H, L);
    reinterpret_cast<ull*>(g_Whi)[i] = H;
    reinterpret_cast<ull*>(g_Wlo)[i] = L;
}

__global__ void __launch_bounds__(THREADS, 1)
router_kernel(const float* __restrict__ x, float* __restrict__ out, int T)
{
    extern __shared__ __align__(128) char dsm[];
    const uint32_t sb = smem_u32(dsm);

    const int tid = threadIdx.x;
    const int wid = tid >> 5;
    const int lane = tid & 31;
    const int row0 = blockIdx.x * TM;

    // barrier ids: full[s]=1+s (1..3), empty[s]=4+s (4..6)
    float acc[2][4][4];   // [m-tile][n8][4]
#pragma unroll
    for (int m = 0; m < 2; m++)
#pragma unroll
        for (int g = 0; g < 4; g++)
#pragma unroll
            for (int j = 0; j < 4; j++) acc[m][g][j] = 0.f;

    if (wid >= 8) {
        // ================= PRODUCER (warps 8-11, 128 threads) =================
        const int tp = tid - 256;   // 0..127
        float4 ax[16];
        uint4 bh[4], bl[4];

        // load chunk 0
#pragma unroll
        for (int i = 0; i < 16; i++) {
            const int f = i * 128 + tp;              // 0..2047
            const int grow = row0 + (f >> 4);        // rows 0..127
            ax[i] = (grow < T)
                ? *reinterpret_cast<const float4*>(x + (size_t)grow * 2048 + (f & 15) * 4)
                : make_float4(0.f, 0.f, 0.f, 0.f);
        }
#pragma unroll
        for (int i = 0; i < 4; i++) {
            const int f = i * 128 + tp;              // 0..511
            const int rr = f >> 3;                   // 0..63
            const int cc = f & 7;
            bh[i] = *reinterpret_cast<const uint4*>(g_Whi + (size_t)rr * 2048 + cc * 8);
            bl[i] = *reinterpret_cast<const uint4*>(g_Wlo + (size_t)rr * 2048 + cc * 8);
        }

        for (int c = 0; c < NCH; c++) {
            const int s = c % NSTG;
            const uint32_t off = (uint32_t)s * BUFSZ;
            const uint32_t tb = sb + off;

            if (c >= NSTG) BAR_SYNC(4 + s);   // wait consumers freed this stage

#pragma unroll
            for (int i = 0; i < 16; i++) {
                const int f = i * 128 + tp;
                const uint32_t o = (uint32_t)((f >> 4) * ASTR + (f & 15) * 8);
                cvt_store(tb + AHI_O + o, tb + ALO_O + o, ax[i]);
            }
#pragma unroll
            for (int i = 0; i < 4; i++) {
                const int f = i * 128 + tp;
                const uint32_t o = (uint32_t)((f >> 3) * ASTR + (f & 7) * 16);
                *reinterpret_cast<uint4*>(dsm + off + BHI_O + o) = bh[i];
                *reinterpret_cast<uint4*>(dsm + off + BLO_O + o) = bl[i];
            }
            asm volatile("membar.cta;" ::: "memory");
            BAR_ARRIVE(1 + s);             // stage full

            if (c + 1 < NCH) {
                const int k0 = (c + 1) * CK;
#pragma unroll
                for (int i = 0; i < 16; i++) {
                    const int f = i * 128 + tp;
                    const int grow = row0 + (f >> 4);
                    if (grow < T)
                        ax[i] = *reinterpret_cast<const float4*>(
                            x + (size_t)grow * 2048 + k0 + (f & 15) * 4);
                }
#pragma unroll
                for (int i = 0; i < 4; i++) {
                    const int f = i * 128 + tp;
                    const int rr = f >> 3;
                    const int cc = f & 7;
                    bh[i] = *reinterpret_cast<const uint4*>(
                        g_Whi + (size_t)rr * 2048 + k0 + cc * 8);
                    bl[i] = *reinterpret_cast<const uint4*>(
                        g_Wlo + (size_t)rr * 2048 + k0 + cc * 8);
                }
            }
        }
    } else {
        // ================= CONSUMER (warps 0-7): 32 tokens x 32 experts =======
        const int sr = (wid >> 1) * 32;      // token strip 0..3
        const int eh = (wid & 1) * 32;       // expert half

        const uint32_t a_base0 = (uint32_t)((sr + (lane & 15)) * ASTR
                                            + ((lane >> 4) << 4));
        const uint32_t a_base1 = a_base0 + 16 * ASTR;
        const uint32_t b_base = (uint32_t)((eh + (lane & 7) + ((lane >> 4) & 1) * 8) * ASTR
                                           + (((lane >> 3) & 1) << 4));

        // double-buffered fragments
        uint32_t ah[2][2][4], al[2][2][4];   // [buf][m][4]
        uint32_t vh[2][2][4], vl[2][2][4];   // [buf][jpair][4]

        for (int c = 0; c < NCH; c++) {
            const int s = c % NSTG;
            const uint32_t tb = sb + (uint32_t)s * BUFSZ;
            BAR_SYNC(1 + s);               // wait stage full

            // preload kk=0 fragments into buf 0
            ldm4(ah[0][0], tb + AHI_O + a_base0);
            ldm4(ah[0][1], tb + AHI_O + a_base1);
            ldm4(al[0][0], tb + ALO_O + a_base0);
            ldm4(al[0][1], tb + ALO_O + a_base1);
            ldm4(vh[0][0], tb + BHI_O + b_base);
            ldm4(vh[0][1], tb + BHI_O + b_base + 16 * ASTR);
            ldm4(vl[0][0], tb + BLO_O + b_base);
            ldm4(vl[0][1], tb + BLO_O + b_base + 16 * ASTR);

#pragma unroll
            for (int kk = 0; kk < 4; kk++) {
                const int cb = kk & 1;
                const int nb = cb ^ 1;
                if (kk < 3) {   // prefetch kk+1 fragments (hidden under HMMAs)
                    const uint32_t ko = (uint32_t)(kk + 1) * 32;
                    ldm4(ah[nb][0], tb + AHI_O + a_base0 + ko);
                    ldm4(ah[nb][1], tb + AHI_O + a_base1 + ko);
                    ldm4(al[nb][0], tb + ALO_O + a_base0 + ko);
                    ldm4(al[nb][1], tb + ALO_O + a_base1 + ko);
                    ldm4(vh[nb][0], tb + BHI_O + b_base + ko);
                    ldm4(vh[nb][1], tb + BHI_O + b_base + 16 * ASTR + ko);
                    ldm4(vl[nb][0], tb + BLO_O + b_base + ko);
                    ldm4(vl[nb][1], tb + BLO_O + b_base + 16 * ASTR + ko);
                }
#pragma unroll
                for (int m = 0; m < 2; m++)
#pragma unroll
                    for (int jp = 0; jp < 2; jp++)
#pragma unroll
                        for (int tt = 0; tt < 2; tt++) {
                            float* dd = acc[m][jp * 2 + tt];
                            mma16816(dd, ah[cb][m], vh[cb][jp][tt * 2], vh[cb][jp][tt * 2 + 1]);
                            mma16816(dd, ah[cb][m], vl[cb][jp][tt * 2], vl[cb][jp][tt * 2 + 1]);
                            mma16816(dd, al[cb][m], vh[cb][jp][tt * 2], vh[cb][jp][tt * 2 + 1]);
                        }
            }
            BAR_ARRIVE(4 + s);             // stage free
        }
    }

    __syncthreads();

    // ---- dump logits to smem [TM][LS] (consumer warps only) ----
    float* lg = reinterpret_cast<float*>(dsm);
    if (wid < 8) {
        const int sr = (wid >> 1) * 32;
        const int eh = (wid & 1) * 32;
#pragma unroll
        for (int m = 0; m < 2; m++) {
            const int r1 = sr + m * 16 + (lane >> 2);
#pragma unroll
            for (int g = 0; g < 4; g++) {
                const int ec = eh + (g >> 1) * 16 + (g & 1) * 8 + 2 * (lane & 3);
                *reinterpret_cast<float2*>(lg + r1 * LS + ec) =
                    make_float2(acc[m][g][0], acc[m][g][1]);
                *reinterpret_cast<float2*>(lg + (r1 + 8) * LS + ec) =
                    make_float2(acc[m][g][2], acc[m][g][3]);
            }
        }
    }
    __syncthreads();

    // ---- epilogue: one thread = one token (threads 0..127) ----
    if (tid >= TM) return;
    const int row = row0 + tid;
    if (row >= T) return;

    float l[64];
#pragma unroll
    for (int e = 0; e < 64; e += 4) {
        const float4 v = *reinterpret_cast<const float4*>(lg + tid * LS + e);
        l[e] = v.x; l[e + 1] = v.y; l[e + 2] = v.z; l[e + 3] = v.w;
    }

    // top-2 (earliest index wins ties, matching lax.top_k)
    float m1 = -3.402823466e38f, m2 = -3.402823466e38f;
    int i1 = 0, i2 = 0;
#pragma unroll
    for (int e = 0; e < 64; e++) {
        const float v = l[e];
        if (v > m1) { m2 = m1; i2 = i1; m1 = v; i1 = e; }
        else if (v > m2) { m2 = v; i2 = e; }
    }

    float s = 0.f;
    float p[64];
#pragma unroll
    for (int e = 0; e < 64; e++) {
        p[e] = __expf(l[e] - m1);
        s += p[e];
    }
    const float inv = 1.0f / s;

    const float p1 = p[i1] * inv;
    const float p2 = p[i2] * inv;
    const float rs = 1.0f / (p1 + p2);

    const size_t Tz = (size_t)T;
    float* mask = out;
    float* idxo = out + Tz * 64;
    float* rp   = out + Tz * 64 + Tz * 2;
    float* pr   = out + Tz * 64 + Tz * 2 + Tz * 64;
    const size_t gt = (size_t)row;

#pragma unroll
    for (int e = 0; e < 64; e += 4) {
        float4 pv4, m4, r4;
        float* pvp = &pv4.x; float* mp = &m4.x; float* rpp = &r4.x;
#pragma unroll
        for (int j = 0; j < 4; j++) {
            const int ee = e + j;
            const float pv = p[ee] * inv;
            const bool sel = (ee == i1) | (ee == i2);
            pvp[j] = pv;
            mp[j] = sel ? 1.0f : 0.0f;
            rpp[j] = sel ? pv * rs : 0.0f;
        }
        *reinterpret_cast<float4*>(pr + gt * 64 + e) = pv4;
        *reinterpret_cast<float4*>(mask + gt * 64 + e) = m4;
        *reinterpret_cast<float4*>(rp + gt * 64 + e) = r4;
    }
    idxo[gt * 2 + 0] = (float)i1;
    idxo[gt * 2 + 1] = (float)i2;
}

extern "C" void kernel_launch(void* const* d_in, const int* in_sizes, int n_in,
                              void* d_out, int out_size)
{
    const float* x = (const float*)d_in[0];
    const float* W = (const float*)d_in[1];
    const int T = in_sizes[0] / 2048;

    wprep_kernel<<<128, 256>>>(W);

    cudaFuncSetAttribute(router_kernel,
                         cudaFuncAttributeMaxDynamicSharedMemorySize, SMEMB);
    const int blocks = (T + TM - 1) / TM;
    router_kernel<<<blocks, THREADS, SMEMB>>>(x, (float*)d_out, T);
}

// round 13
// speedup vs baseline: 1.0653x; 1.0561x over previous
#include <cuda_runtime.h>
#include <cuda_bf16.h>
#include <cstdint>

// Router: logits = x @ W^T via split-bf16 mma.sync (3 terms).
// All smem staging via cp.async (zero STS): x staged as raw fp32 and converted
// to bf16 hi/lo in consumer registers; W pre-converted once per launch.
// 3-stage ring, one cheap bar.sync per chunk.
// Outputs concatenated fp32: mask[T*64] | idx[T*2] | router_probs[T*64] | probs[T*64]

#define THREADS 256
#define TM 128            // tokens per CTA
#define CK 64             // K chunk
#define NCH (2048 / CK)   // 32
#define NSTG 3
#define APITCH 288        // A fp32 row pitch bytes (64*4 + 32 pad; conflict-free LDS.64)
#define BSTR 144          // B bf16 row stride bytes

// per-stage layout (bytes)
#define A_O   0
#define BHI_O 36864       // 128*288
#define BLO_O 46080       // +64*144
#define BUFSZ 55296
#define SMEMB (NSTG * BUFSZ)   // 165888
#define LS 68             // logits row stride (floats)

typedef unsigned long long ull;

__device__ __nv_bfloat16 g_Whi[64 * 2048];
__device__ __nv_bfloat16 g_Wlo[64 * 2048];

__device__ __forceinline__ uint32_t smem_u32(const void* p) {
    uint32_t a;
    asm("{ .reg .u64 t; cvta.to.shared.u64 t, %1; cvt.u32.u64 %0, t; }"
        : "=r"(a) : "l"(p));
    return a;
}

__device__ __forceinline__ void ldm4(uint32_t* r, uint32_t addr) {
    asm volatile("ldmatrix.sync.aligned.m8n8.x4.shared.b16 {%0,%1,%2,%3}, [%4];"
        : "=r"(r[0]), "=r"(r[1]), "=r"(r[2]), "=r"(r[3]) : "r"(addr));
}

// register-only, non-volatile: ptxas may schedule freely
__device__ __forceinline__ void mma16816(float* d, const uint32_t* a,
                                         uint32_t b0, uint32_t b1) {
    asm("mma.sync.aligned.m16n8k16.row.col.f32.bf16.bf16.f32 "
        "{%0,%1,%2,%3}, {%4,%5,%6,%7}, {%8,%9}, {%0,%1,%2,%3};"
        : "+f"(d[0]), "+f"(d[1]), "+f"(d[2]), "+f"(d[3])
        : "r"(a[0]), "r"(a[1]), "r"(a[2]), "r"(a[3]), "r"(b0), "r"(b1));
}

// float2 -> bf16x2 hi + bf16x2 lo (residual)
__device__ __forceinline__ void split2(float2 v, uint32_t& hi, uint32_t& lo) {
    asm("cvt.rn.bf16x2.f32 %0, %1, %2;" : "=r"(hi) : "f"(v.y), "f"(v.x));
    const float h0 = __uint_as_float(hi << 16);
    const float h1 = __uint_as_float(hi & 0xffff0000u);
    asm("cvt.rn.bf16x2.f32 %0, %1, %2;" : "=r"(lo) : "f"(v.y - h1), "f"(v.x - h0));
}

// fp32x4 -> bf16 hi x4 (8B) + bf16 lo x4 (8B) (wprep only)
__device__ __forceinline__ void split4(float4 v, ull& H, ull& L) {
    uint32_t h0, h1, l0, l1;
    split2(make_float2(v.x, v.y), h0, l0);
    split2(make_float2(v.z, v.w), h1, l1);
    asm("mov.b64 %0, {%1, %2};" : "=l"(H) : "r"(h0), "r"(h1));
    asm("mov.b64 %0, {%1, %2};" : "=l"(L) : "r"(l0), "r"(l1));
}

__device__ __forceinline__ void cpa16(uint32_t dst, const void* src) {
    asm volatile("cp.async.cg.shared.global [%0], [%1], 16;"
                 :: "r"(dst), "l"(src) : "memory");
}
__device__ __forceinline__ void cpa16z(uint32_t dst, const void* src, int sz) {
    asm volatile("cp.async.cg.shared.global [%0], [%1], 16, %2;"
                 :: "r"(dst), "l"(src), "r"(sz) : "memory");
}

// ---- pre-kernel: convert W (64x2048 fp32) -> bf16 hi/lo ----
__global__ void __launch_bounds__(256)
wprep_kernel(const float* __restrict__ W)
{
    const int i = blockIdx.x * 256 + threadIdx.x;   // 0..32767 float4s
    const float4 v = reinterpret_cast<const float4*>(W)[i];
    ull H, L;
    split4(v, H, L);
    reinterpret_cast<ull*>(g_Whi)[i] = H;
    reinterpret_cast<ull*>(g_Wlo)[i] = L;
}

__global__ void __launch_bounds__(THREADS, 1)
router_kernel(const float* __restrict__ x, float* __restrict__ out, int T)
{
    extern __shared__ __align__(128) char dsm[];
    const uint32_t sb = smem_u32(dsm);

    const int tid = threadIdx.x;
    const int wid = tid >> 5;
    const int lane = tid & 31;
    const int row0 = blockIdx.x * TM;

    // ---- cp.async issue for one chunk into one stage ----
    auto issue_stage = [&](int kc, uint32_t off) {
        const int k0 = kc * CK;
        // A: 128 rows x 16 float4 = 2048 ops, 8 per thread (raw fp32)
#pragma unroll
        for (int i = 0; i < 8; i++) {
            const int f = i * THREADS + tid;
            const int ar = f >> 4;
            const int grow = row0 + ar;
            const int gsrc = (grow < T) ? grow : (T - 1);
            cpa16z(sb + off + A_O + (uint32_t)(ar * APITCH + (f & 15) * 16),
                   x + (size_t)gsrc * 2048 + k0 + (f & 15) * 4,
                   (grow < T) ? 16 : 0);
        }
        // W hi/lo: 64 rows x 8 x 16B = 512 ops each, 2 per thread
#pragma unroll
        for (int i = 0; i < 2; i++) {
            const int f = i * THREADS + tid;
            const int rr = f >> 3;
            const int cc = f & 7;
            cpa16(sb + off + BHI_O + (uint32_t)(rr * BSTR + cc * 16),
                  g_Whi + (size_t)rr * 2048 + k0 + cc * 8);
            cpa16(sb + off + BLO_O + (uint32_t)(rr * BSTR + cc * 16),
                  g_Wlo + (size_t)rr * 2048 + k0 + cc * 8);
        }
    };

    // prologue: stages 0 and 1 in flight
    issue_stage(0, 0);
    asm volatile("cp.async.commit_group;" ::: "memory");
    issue_stage(1, BUFSZ);
    asm volatile("cp.async.commit_group;" ::: "memory");

    // consumer tile: 32 tokens x 32 experts per warp
    const int sr = (wid >> 1) * 32;
    const int eh = (wid & 1) * 32;
    const int r = lane >> 2;
    const int c2 = (lane & 3) * 2;
    const uint32_t b_base = (uint32_t)((eh + (lane & 7) + ((lane >> 4) & 1) * 8) * BSTR
                                       + (((lane >> 3) & 1) << 4));

    float acc[2][4][4];
#pragma unroll
    for (int m = 0; m < 2; m++)
#pragma unroll
        for (int g = 0; g < 4; g++)
#pragma unroll
            for (int j = 0; j < 4; j++) acc[m][g][j] = 0.f;

    for (int c = 0; c < NCH; c++) {
        if (c != NCH - 1) {
            asm volatile("cp.async.wait_group 1;" ::: "memory");
        } else {
            asm volatile("cp.async.wait_group 0;" ::: "memory");
        }
        __syncthreads();   // publish stage c; no STS pending -> cheap

        if (c + 2 < NCH) {
            issue_stage(c + 2, (uint32_t)((c + 2) % NSTG) * BUFSZ);
            asm volatile("cp.async.commit_group;" ::: "memory");
        }

        const uint32_t off = (uint32_t)(c % NSTG) * BUFSZ;
        const uint32_t tb = sb + off;
        const char* Ab = dsm + off + A_O;

#pragma unroll
        for (int kk = 0; kk < 4; kk++) {
            // ---- A fragments: LDS fp32 + in-register bf16 split ----
            uint32_t ah[2][4], al[2][4];
#pragma unroll
            for (int m = 0; m < 2; m++) {
                const char* p = Ab + (sr + m * 16 + r) * APITCH + (kk * 16 + c2) * 4;
                const float2 v0 = *reinterpret_cast<const float2*>(p);
                const float2 v1 = *reinterpret_cast<const float2*>(p + 8 * APITCH);
                const float2 v2 = *reinterpret_cast<const float2*>(p + 32);
                const float2 v3 = *reinterpret_cast<const float2*>(p + 8 * APITCH + 32);
                split2(v0, ah[m][0], al[m][0]);
                split2(v1, ah[m][1], al[m][1]);
                split2(v2, ah[m][2], al[m][2]);
                split2(v3, ah[m][3], al[m][3]);
            }
            // ---- B fragments ----
            uint32_t vh[2][4], vl[2][4];
            const uint32_t ko = (uint32_t)kk * 32;
#pragma unroll
            for (int jp = 0; jp < 2; jp++) {
                ldm4(vh[jp], tb + BHI_O + b_base + (uint32_t)(jp * 16 * BSTR) + ko);
                ldm4(vl[jp], tb + BLO_O + b_base + (uint32_t)(jp * 16 * BSTR) + ko);
            }
            // ---- MMAs ----
#pragma unroll
            for (int m = 0; m < 2; m++)
#pragma unroll
                for (int jp = 0; jp < 2; jp++)
#pragma unroll
                    for (int tt = 0; tt < 2; tt++) {
                        float* dd = acc[m][jp * 2 + tt];
                        mma16816(dd, ah[m], vh[jp][tt * 2], vh[jp][tt * 2 + 1]);
                        mma16816(dd, ah[m], vl[jp][tt * 2], vl[jp][tt * 2 + 1]);
                        mma16816(dd, al[m], vh[jp][tt * 2], vh[jp][tt * 2 + 1]);
                    }
        }
    }

    __syncthreads();

    // ---- dump logits to smem [TM][LS] ----
    float* lg = reinterpret_cast<float*>(dsm);
#pragma unroll
    for (int m = 0; m < 2; m++) {
        const int r1 = sr + m * 16 + (lane >> 2);
#pragma unroll
        for (int g = 0; g < 4; g++) {
            const int ec = eh + (g >> 1) * 16 + (g & 1) * 8 + 2 * (lane & 3);
            *reinterpret_cast<float2*>(lg + r1 * LS + ec) =
                make_float2(acc[m][g][0], acc[m][g][1]);
            *reinterpret_cast<float2*>(lg + (r1 + 8) * LS + ec) =
                make_float2(acc[m][g][2], acc[m][g][3]);
        }
    }
    __syncthreads();

    // ---- epilogue: one thread = one token (threads 0..127) ----
    if (tid >= TM) return;
    const int row = row0 + tid;
    if (row >= T) return;

    float l[64];
#pragma unroll
    for (int e = 0; e < 64; e += 4) {
        const float4 v = *reinterpret_cast<const float4*>(lg + tid * LS + e);
        l[e] = v.x; l[e + 1] = v.y; l[e + 2] = v.z; l[e + 3] = v.w;
    }

    // top-2 (earliest index wins ties, matching lax.top_k)
    float m1 = -3.402823466e38f, m2 = -3.402823466e38f;
    int i1 = 0, i2 = 0;
#pragma unroll
    for (int e = 0; e < 64; e++) {
        const float v = l[e];
        if (v > m1) { m2 = m1; i2 = i1; m1 = v; i1 = e; }
        else if (v > m2) { m2 = v; i2 = e; }
    }

    float s = 0.f;
    float p[64];
#pragma unroll
    for (int e = 0; e < 64; e++) {
        p[e] = __expf(l[e] - m1);
        s += p[e];
    }
    const float inv = 1.0f / s;

    const float p1 = p[i1] * inv;
    const float p2 = p[i2] * inv;
    const float rs = 1.0f / (p1 + p2);

    const size_t Tz = (size_t)T;
    float* mask = out;
    float* idxo = out + Tz * 64;
    float* rp   = out + Tz * 64 + Tz * 2;
    float* pr   = out + Tz * 64 + Tz * 2 + Tz * 64;
    const size_t gt = (size_t)row;

#pragma unroll
    for (int e = 0; e < 64; e += 4) {
        float4 pv4, m4, r4;
        float* pvp = &pv4.x; float* mp = &m4.x; float* rpp = &r4.x;
#pragma unroll
        for (int j = 0; j < 4; j++) {
            const int ee = e + j;
            const float pv = p[ee] * inv;
            const bool sel = (ee == i1) | (ee == i2);
            pvp[j] = pv;
            mp[j] = sel ? 1.0f : 0.0f;
            rpp[j] = sel ? pv * rs : 0.0f;
        }
        *reinterpret_cast<float4*>(pr + gt * 64 + e) = pv4;
        *reinterpret_cast<float4*>(mask + gt * 64 + e) = m4;
        *reinterpret_cast<float4*>(rp + gt * 64 + e) = r4;
    }
    idxo[gt * 2 + 0] = (float)i1;
    idxo[gt * 2 + 1] = (float)i2;
}

extern "C" void kernel_launch(void* const* d_in, const int* in_sizes, int n_in,
                              void* d_out, int out_size)
{
    const float* x = (const float*)d_in[0];
    const float* W = (const float*)d_in[1];
    const int T = in_sizes[0] / 2048;

    wprep_kernel<<<128, 256>>>(W);

    cudaFuncSetAttribute(router_kernel,
                         cudaFuncAttributeMaxDynamicSharedMemorySize, SMEMB);
    const int blocks = (T + TM - 1) / TM;
    router_kernel<<<blocks, THREADS, SMEMB>>>(x, (float*)d_out, T);
}